// round 2
// baseline (speedup 1.0000x reference)
#include <cuda_runtime.h>
#include <cuda_bf16.h>
#include <math.h>

#define Bn 32
#define Tn 384
#define Dn 768
#define D3 2304
#define NB 96
#define THRESH 0.95f

__device__ float g_xp[(size_t)Bn * Tn * D3];
__device__ float g_states[(size_t)Bn * Tn * Dn];
__device__ float g_h[2][Bn][Dn];
__device__ float g_probs[Bn * Tn];
__device__ float g_weights[Bn * Tn];
__device__ int   g_segend[Bn * Tn];
__device__ int   g_nsegs[Bn];
__device__ volatile int g_flag[NB];
__device__ int   g_done;

// ============ Kernel 1: xp = emb[sent] @ w_ih^T + b_ih  (12288 x 2304 x 768)
#define BM 128
#define BN 128
#define BK 16

__global__ __launch_bounds__(256) void k_xp(const int* __restrict__ sent,
                                            const float* __restrict__ emb,
                                            const float* __restrict__ w_ih,
                                            const float* __restrict__ b_ih) {
    __shared__ float As[BK][BM + 4];
    __shared__ float Bs[BK][BN + 4];
    __shared__ int toks[BM];

    const int tid = threadIdx.x;
    const int bm = blockIdx.y * BM;
    const int bn = blockIdx.x * BN;
    const int tx = tid & 15;
    const int ty = tid >> 4;
    const int lm = tid >> 2;
    const int lk4 = tid & 3;

    if (tid < BM) toks[tid] = sent[bm + tid];
    __syncthreads();

    float acc[8][8];
#pragma unroll
    for (int i = 0; i < 8; i++)
#pragma unroll
        for (int j = 0; j < 8; j++) acc[i][j] = 0.f;

    for (int kt = 0; kt < Dn; kt += BK) {
#pragma unroll
        for (int p = 0; p < 2; p++) {
            int m = lm + p * 64;
            float4 va = *(const float4*)(emb + (size_t)toks[m] * Dn + kt + lk4 * 4);
            As[lk4 * 4 + 0][m] = va.x; As[lk4 * 4 + 1][m] = va.y;
            As[lk4 * 4 + 2][m] = va.z; As[lk4 * 4 + 3][m] = va.w;
            float4 vb = *(const float4*)(w_ih + (size_t)(bn + m) * Dn + kt + lk4 * 4);
            Bs[lk4 * 4 + 0][m] = vb.x; Bs[lk4 * 4 + 1][m] = vb.y;
            Bs[lk4 * 4 + 2][m] = vb.z; Bs[lk4 * 4 + 3][m] = vb.w;
        }
        __syncthreads();
#pragma unroll
        for (int k = 0; k < BK; k++) {
            float4 a0 = *(const float4*)&As[k][ty * 8];
            float4 a1 = *(const float4*)&As[k][ty * 8 + 4];
            float4 b0 = *(const float4*)&Bs[k][tx * 4];
            float4 b1 = *(const float4*)&Bs[k][64 + tx * 4];
            float av[8] = {a0.x, a0.y, a0.z, a0.w, a1.x, a1.y, a1.z, a1.w};
            float bv[8] = {b0.x, b0.y, b0.z, b0.w, b1.x, b1.y, b1.z, b1.w};
#pragma unroll
            for (int i = 0; i < 8; i++)
#pragma unroll
                for (int j = 0; j < 8; j++) acc[i][j] += av[i] * bv[j];
        }
        __syncthreads();
    }

    float4 bias0 = *(const float4*)&b_ih[bn + tx * 4];
    float4 bias1 = *(const float4*)&b_ih[bn + 64 + tx * 4];
#pragma unroll
    for (int i = 0; i < 8; i++) {
        int row = bm + ty * 8 + i;
        float* orow = g_xp + (size_t)row * D3 + bn;
        float4 v0 = {acc[i][0] + bias0.x, acc[i][1] + bias0.y,
                     acc[i][2] + bias0.z, acc[i][3] + bias0.w};
        float4 v1 = {acc[i][4] + bias1.x, acc[i][5] + bias1.y,
                     acc[i][6] + bias1.z, acc[i][7] + bias1.w};
        *(float4*)&orow[tx * 4] = v0;
        *(float4*)&orow[64 + tx * 4] = v1;
    }
}

// ============ Kernel 2: persistent GRU scan. Block owns 8 h-columns.
// SMEM: w_s [24][772] (w_hh slice) + part [8][24][33] (k-split partials)
#define SM_WS (24 * 772)
#define SM_PART (8 * 24 * 33)
#define SMEM_GRU ((SM_WS + SM_PART) * 4)

__device__ __forceinline__ void gbar(int phase) {
    __syncthreads();
    if (threadIdx.x == 0) {
        __threadfence();
        g_flag[blockIdx.x] = phase;
    }
    if ((int)threadIdx.x < NB) {
        while (g_flag[threadIdx.x] < phase) {}
    }
    __threadfence();
    __syncthreads();
}

__global__ __launch_bounds__(256, 1) void k_gru(const float* __restrict__ w_hh,
                                                const float* __restrict__ b_hh) {
    extern __shared__ float sm[];
    float* w_s = sm;
    float* part = sm + SM_WS;

    const int tid = threadIdx.x;
    const int bid = blockIdx.x;
    const int c0 = bid * 8;

    // resident w_hh slice: local rows 0..7 = r-gate, 8..15 = z, 16..23 = n
    for (int i = tid; i < 24 * 192; i += 256) {
        int lr = i / 192, k4 = i - lr * 192;
        int gr = (lr < 8) ? (c0 + lr) : (lr < 16) ? (Dn + c0 + lr - 8)
                                                  : (2 * Dn + c0 + lr - 16);
        *(float4*)(w_s + lr * 772 + k4 * 4) =
            *(const float4*)(w_hh + (size_t)gr * Dn + k4 * 4);
    }

    const int gc = tid >> 5;  // gate-phase: local column 0..7
    const int gb = tid & 31;  // gate-phase: batch
    const float br = b_hh[c0 + gc];
    const float bz = b_hh[Dn + c0 + gc];
    const float bnn = b_hh[2 * Dn + c0 + gc];

    const int lane = tid & 31;
    const int ks = tid >> 5;      // warp = k-split chunk of 96
    const int rp = lane >> 2;     // rows rp*3..rp*3+2
    const int bp = lane & 3;      // batches bp+4j
    const int kb4 = ks * 24;      // k-chunk base in float4 units

    // zero h parity 0 (NB*256 == Bn*Dn)
    (&g_h[0][0][0])[bid * 256 + tid] = 0.f;
    gbar(1);

    for (int t = 0; t < Tn; t++) {
        const int par = t & 1;

        size_t mrow = (size_t)(gb * Tn + t) * D3 + c0 + gc;
        float xr = g_xp[mrow];
        float xz = g_xp[mrow + Dn];
        float xn = g_xp[mrow + 2 * Dn];

        float acc[3][8];
#pragma unroll
        for (int i = 0; i < 3; i++)
#pragma unroll
            for (int j = 0; j < 8; j++) acc[i][j] = 0.f;

        const float* wb = w_s + (rp * 3) * 772 + ks * 96;
        const float4* hb = (const float4*)(&g_h[par][0][0]);  // [32][192]
#pragma unroll 4
        for (int k4 = 0; k4 < 24; k4++) {
            float4 w0 = *(const float4*)(wb + k4 * 4);
            float4 w1 = *(const float4*)(wb + 772 + k4 * 4);
            float4 w2 = *(const float4*)(wb + 1544 + k4 * 4);
#pragma unroll
            for (int j = 0; j < 8; j++) {
                float4 hv = __ldcv(hb + (bp + 4 * j) * 192 + kb4 + k4);
                acc[0][j] += w0.x * hv.x + w0.y * hv.y + w0.z * hv.z + w0.w * hv.w;
                acc[1][j] += w1.x * hv.x + w1.y * hv.y + w1.z * hv.z + w1.w * hv.w;
                acc[2][j] += w2.x * hv.x + w2.y * hv.y + w2.z * hv.z + w2.w * hv.w;
            }
        }
#pragma unroll
        for (int i = 0; i < 3; i++)
#pragma unroll
            for (int j = 0; j < 8; j++)
                part[ks * 792 + (rp * 3 + i) * 33 + (bp + 4 * j)] = acc[i][j];
        __syncthreads();

        float hr = br, hz = bz, hn = bnn;
#pragma unroll
        for (int s2 = 0; s2 < 8; s2++) {
            hr += part[s2 * 792 + gc * 33 + gb];
            hz += part[s2 * 792 + (8 + gc) * 33 + gb];
            hn += part[s2 * 792 + (16 + gc) * 33 + gb];
        }
        float hold = __ldcv(&g_h[par][gb][c0 + gc]);
        float r = 1.f / (1.f + expf(-(xr + hr)));
        float z = 1.f / (1.f + expf(-(xz + hz)));
        float n = tanhf(xn + r * hn);
        float hnew = (1.f - z) * n + z * hold;
        g_h[par ^ 1][gb][c0 + gc] = hnew;
        g_states[(size_t)(gb * Tn + t) * Dn + c0 + gc] = hnew;

        gbar(t + 2);
    }

    // departure-counted barrier reset (safe for graph replay)
    if (tid == 0) {
        int old = atomicAdd(&g_done, 1);
        if (old == NB - 1) {
            for (int i = 0; i < NB; i++) g_flag[i] = 0;
            __threadfence();
            g_done = 0;
        }
    }
}

// ============ Kernel 3: probs = sigmoid(states @ w_act + b_act)
__global__ __launch_bounds__(256) void k_probs(const float* __restrict__ w_act,
                                               const float* __restrict__ b_act,
                                               float* __restrict__ out_probs) {
    int warp = threadIdx.x >> 5, lane = threadIdx.x & 31;
    int m = blockIdx.x * 8 + warp;
    const float4* row = (const float4*)(g_states + (size_t)m * Dn);
    const float4* wv = (const float4*)w_act;
    float acc = 0.f;
    for (int i = lane; i < 192; i += 32) {
        float4 v = row[i], w = wv[i];
        acc += v.x * w.x + v.y * w.y + v.z * w.z + v.w * w.w;
    }
#pragma unroll
    for (int off = 16; off; off >>= 1) acc += __shfl_down_sync(0xffffffffu, acc, off);
    if (lane == 0) {
        float p = 1.f / (1.f + expf(-(acc + b_act[0])));
        g_probs[m] = p;
        out_probs[m] = p;
    }
}

// ============ Kernel 4: ACT halting scan (lane = batch row)
__global__ void k_halt() {
    int b = threadIdx.x;
    if (b >= Bn) return;
    const float* pb = g_probs + b * Tn;
    float acc = 0.f;
    int ns = 0;
    float p = pb[0];
    for (int t = 0; t < Tn; t++) {
        float pn = (t + 1 < Tn) ? pb[t + 1] : 0.f;
        float a = acc + p;
        if (a > THRESH) {
            g_weights[b * Tn + t] = p - (a - 1.f);
            g_segend[b * Tn + ns] = t;
            ns++;
            acc = 0.f;
        } else {
            g_weights[b * Tn + t] = p;
            acc = a;
        }
        p = pn;
    }
    g_nsegs[b] = ns;
}

// ============ Kernel 5: segment sums -> output embs (zero-padded)
__global__ __launch_bounds__(128) void k_out(float* __restrict__ out) {
    int bs = blockIdx.x;
    int b = bs / Tn, s = bs - b * Tn;
    float* o = out + (size_t)bs * Dn;
    int tid = threadIdx.x;
    if (s >= g_nsegs[b]) {
        for (int d = tid; d < Dn; d += 128) o[d] = 0.f;
        return;
    }
    int t1 = g_segend[b * Tn + s];
    int t0 = (s == 0) ? 0 : g_segend[b * Tn + s - 1] + 1;
    for (int d = tid; d < Dn; d += 128) {
        float sum = 0.f;
        for (int t = t0; t <= t1; t++)
            sum += g_states[(size_t)(b * Tn + t) * Dn + d] * g_weights[b * Tn + t];
        o[d] = sum;
    }
}

extern "C" void kernel_launch(void* const* d_in, const int* in_sizes, int n_in,
                              void* d_out, int out_size) {
    const int* sent    = (const int*)d_in[0];
    const float* emb   = (const float*)d_in[1];
    const float* w_ih  = (const float*)d_in[2];
    const float* w_hh  = (const float*)d_in[3];
    const float* b_ih  = (const float*)d_in[4];
    const float* b_hh  = (const float*)d_in[5];
    const float* w_act = (const float*)d_in[6];
    const float* b_act = (const float*)d_in[7];
    float* out = (float*)d_out;

    cudaFuncSetAttribute(k_gru, cudaFuncAttributeMaxDynamicSharedMemorySize, SMEM_GRU);

    k_xp<<<dim3(D3 / BN, (Bn * Tn) / BM), 256>>>(sent, emb, w_ih, b_ih);
    k_gru<<<NB, 256, SMEM_GRU>>>(w_hh, b_hh);
    k_probs<<<(Bn * Tn) / 8, 256>>>(w_act, b_act, out + (size_t)Bn * Tn * Dn);
    k_halt<<<1, 32>>>();
    k_out<<<Bn * Tn, 128>>>(out);
}

// round 3
// speedup vs baseline: 1.5146x; 1.5146x over previous
#include <cuda_runtime.h>
#include <cuda_bf16.h>
#include <math.h>

#define Bn 32
#define Tn 384
#define Dn 768
#define D3 2304
#define NB 96
#define THRESH 0.95f

__device__ float g_xp[(size_t)Bn * Tn * D3];
__device__ float g_states[(size_t)Bn * Tn * Dn];
__device__ float g_h[2][Bn][Dn];
__device__ float g_probs[Bn * Tn];
__device__ float g_weights[Bn * Tn];
__device__ int   g_segend[Bn * Tn];
__device__ int   g_nsegs[Bn];
__device__ volatile int g_flag[NB];
__device__ int   g_done;

// ============ Kernel 1: xp = emb[sent] @ w_ih^T + b_ih  (12288 x 2304 x 768)
#define BM 128
#define BN 128
#define BK 16

__global__ __launch_bounds__(256) void k_xp(const int* __restrict__ sent,
                                            const float* __restrict__ emb,
                                            const float* __restrict__ w_ih,
                                            const float* __restrict__ b_ih) {
    __shared__ float As[BK][BM + 4];
    __shared__ float Bs[BK][BN + 4];
    __shared__ int toks[BM];

    const int tid = threadIdx.x;
    const int bm = blockIdx.y * BM;
    const int bn = blockIdx.x * BN;
    const int tx = tid & 15;
    const int ty = tid >> 4;
    const int lm = tid >> 2;
    const int lk4 = tid & 3;

    if (tid < BM) toks[tid] = sent[bm + tid];
    __syncthreads();

    float acc[8][8];
#pragma unroll
    for (int i = 0; i < 8; i++)
#pragma unroll
        for (int j = 0; j < 8; j++) acc[i][j] = 0.f;

    for (int kt = 0; kt < Dn; kt += BK) {
#pragma unroll
        for (int p = 0; p < 2; p++) {
            int m = lm + p * 64;
            float4 va = *(const float4*)(emb + (size_t)toks[m] * Dn + kt + lk4 * 4);
            As[lk4 * 4 + 0][m] = va.x; As[lk4 * 4 + 1][m] = va.y;
            As[lk4 * 4 + 2][m] = va.z; As[lk4 * 4 + 3][m] = va.w;
            float4 vb = *(const float4*)(w_ih + (size_t)(bn + m) * Dn + kt + lk4 * 4);
            Bs[lk4 * 4 + 0][m] = vb.x; Bs[lk4 * 4 + 1][m] = vb.y;
            Bs[lk4 * 4 + 2][m] = vb.z; Bs[lk4 * 4 + 3][m] = vb.w;
        }
        __syncthreads();
#pragma unroll
        for (int k = 0; k < BK; k++) {
            float4 a0 = *(const float4*)&As[k][ty * 8];
            float4 a1 = *(const float4*)&As[k][ty * 8 + 4];
            float4 b0 = *(const float4*)&Bs[k][tx * 4];
            float4 b1 = *(const float4*)&Bs[k][64 + tx * 4];
            float av[8] = {a0.x, a0.y, a0.z, a0.w, a1.x, a1.y, a1.z, a1.w};
            float bv[8] = {b0.x, b0.y, b0.z, b0.w, b1.x, b1.y, b1.z, b1.w};
#pragma unroll
            for (int i = 0; i < 8; i++)
#pragma unroll
                for (int j = 0; j < 8; j++) acc[i][j] += av[i] * bv[j];
        }
        __syncthreads();
    }

    float4 bias0 = *(const float4*)&b_ih[bn + tx * 4];
    float4 bias1 = *(const float4*)&b_ih[bn + 64 + tx * 4];
#pragma unroll
    for (int i = 0; i < 8; i++) {
        int row = bm + ty * 8 + i;
        float* orow = g_xp + (size_t)row * D3 + bn;
        float4 v0 = {acc[i][0] + bias0.x, acc[i][1] + bias0.y,
                     acc[i][2] + bias0.z, acc[i][3] + bias0.w};
        float4 v1 = {acc[i][4] + bias1.x, acc[i][5] + bias1.y,
                     acc[i][6] + bias1.z, acc[i][7] + bias1.w};
        *(float4*)&orow[tx * 4] = v0;
        *(float4*)&orow[64 + tx * 4] = v1;
    }
}

// ============ Kernel 2: persistent GRU scan. Block owns 8 h-columns.
// SMEM: w_s [24][772] + h_s [8 warps][32][100] + part [8][24][33]
#define SM_WS (24 * 772)
#define SM_HS (8 * 32 * 100)
#define SM_PART (8 * 24 * 33)
#define SMEM_GRU ((SM_WS + SM_HS + SM_PART) * 4)

__device__ __forceinline__ void gbar(int phase) {
    __syncthreads();
    if (threadIdx.x == 0) {
        __threadfence();
        g_flag[blockIdx.x] = phase;
    }
    if ((int)threadIdx.x < NB) {
        while (g_flag[threadIdx.x] < phase) {}
    }
    __threadfence();
    __syncthreads();
}

__global__ __launch_bounds__(256, 1) void k_gru(const float* __restrict__ w_hh,
                                                const float* __restrict__ b_hh) {
    extern __shared__ float sm[];
    float* w_s = sm;
    float* h_s = sm + SM_WS;
    float* part = sm + SM_WS + SM_HS;

    const int tid = threadIdx.x;
    const int bid = blockIdx.x;
    const int c0 = bid * 8;

    // resident w_hh slice: local rows 0..7 = r-gate, 8..15 = z, 16..23 = n
    for (int i = tid; i < 24 * 192; i += 256) {
        int lr = i / 192, k4 = i - lr * 192;
        int gr = (lr < 8) ? (c0 + lr) : (lr < 16) ? (Dn + c0 + lr - 8)
                                                  : (2 * Dn + c0 + lr - 16);
        *(float4*)(w_s + lr * 772 + k4 * 4) =
            *(const float4*)(w_hh + (size_t)gr * Dn + k4 * 4);
    }

    const int gc = tid >> 5;  // gate-phase: local column 0..7
    const int gb = tid & 31;  // gate-phase: batch
    const float br = b_hh[c0 + gc];
    const float bz = b_hh[Dn + c0 + gc];
    const float bnn = b_hh[2 * Dn + c0 + gc];

    const int lane = tid & 31;
    const int ks = tid >> 5;      // warp = k-split chunk of 96
    const int rp = lane >> 2;     // rows rp*3..rp*3+2
    const int bp = lane & 3;      // batches bp+4j
    const int kb4 = ks * 24;      // k-chunk base in float4 units

    float* hw = h_s + ks * 3200;  // this warp's staged h slice [32][100]

    // zero h parity 0 (NB*256 == Bn*Dn)
    (&g_h[0][0][0])[bid * 256 + tid] = 0.f;
    gbar(1);

    for (int t = 0; t < Tn; t++) {
        const int par = t & 1;

        size_t mrow = (size_t)(gb * Tn + t) * D3 + c0 + gc;
        float xr = g_xp[mrow];
        float xz = g_xp[mrow + Dn];
        float xn = g_xp[mrow + 2 * Dn];

        // per-warp h staging: warp ks needs only k-columns [24ks,24ks+24) (f4)
        // of all 32 batch rows. 24 coalesced __ldcv float4 per lane, no block sync.
        const float4* gh4 = (const float4*)(&g_h[par][0][0]);  // [32][192] f4
#pragma unroll
        for (int i = 0; i < 24; i++) {
            int idx = i * 32 + lane;          // 0..767 over 32 rows x 24 cols
            int row = idx / 24;
            int col = idx - row * 24;
            float4 v = __ldcv(gh4 + row * 192 + kb4 + col);
            *(float4*)(hw + row * 100 + col * 4) = v;
        }
        __syncwarp();

        float acc[3][8];
#pragma unroll
        for (int i = 0; i < 3; i++)
#pragma unroll
            for (int j = 0; j < 8; j++) acc[i][j] = 0.f;

        const float* wb = w_s + (rp * 3) * 772 + ks * 96;
        const float* hbase = hw + bp * 100;
#pragma unroll 4
        for (int k4 = 0; k4 < 24; k4++) {
            float4 w0 = *(const float4*)(wb + k4 * 4);
            float4 w1 = *(const float4*)(wb + 772 + k4 * 4);
            float4 w2 = *(const float4*)(wb + 1544 + k4 * 4);
#pragma unroll
            for (int j = 0; j < 8; j++) {
                float4 hv = *(const float4*)(hbase + j * 400 + k4 * 4);
                acc[0][j] += w0.x * hv.x + w0.y * hv.y + w0.z * hv.z + w0.w * hv.w;
                acc[1][j] += w1.x * hv.x + w1.y * hv.y + w1.z * hv.z + w1.w * hv.w;
                acc[2][j] += w2.x * hv.x + w2.y * hv.y + w2.z * hv.z + w2.w * hv.w;
            }
        }
#pragma unroll
        for (int i = 0; i < 3; i++)
#pragma unroll
            for (int j = 0; j < 8; j++)
                part[ks * 792 + (rp * 3 + i) * 33 + (bp + 4 * j)] = acc[i][j];
        __syncthreads();

        float hold = __ldcv(&g_h[par][gb][c0 + gc]);
        float hr = br, hz = bz, hn = bnn;
#pragma unroll
        for (int s2 = 0; s2 < 8; s2++) {
            hr += part[s2 * 792 + gc * 33 + gb];
            hz += part[s2 * 792 + (8 + gc) * 33 + gb];
            hn += part[s2 * 792 + (16 + gc) * 33 + gb];
        }
        float r = 1.f / (1.f + expf(-(xr + hr)));
        float z = 1.f / (1.f + expf(-(xz + hz)));
        float n = tanhf(xn + r * hn);
        float hnew = (1.f - z) * n + z * hold;
        g_h[par ^ 1][gb][c0 + gc] = hnew;
        g_states[(size_t)(gb * Tn + t) * Dn + c0 + gc] = hnew;

        gbar(t + 2);
    }

    // departure-counted barrier reset (safe for graph replay)
    if (tid == 0) {
        int old = atomicAdd(&g_done, 1);
        if (old == NB - 1) {
            for (int i = 0; i < NB; i++) g_flag[i] = 0;
            __threadfence();
            g_done = 0;
        }
    }
}

// ============ Kernel 3: probs = sigmoid(states @ w_act + b_act)
__global__ __launch_bounds__(256) void k_probs(const float* __restrict__ w_act,
                                               const float* __restrict__ b_act,
                                               float* __restrict__ out_probs) {
    int warp = threadIdx.x >> 5, lane = threadIdx.x & 31;
    int m = blockIdx.x * 8 + warp;
    const float4* row = (const float4*)(g_states + (size_t)m * Dn);
    const float4* wv = (const float4*)w_act;
    float acc = 0.f;
    for (int i = lane; i < 192; i += 32) {
        float4 v = row[i], w = wv[i];
        acc += v.x * w.x + v.y * w.y + v.z * w.z + v.w * w.w;
    }
#pragma unroll
    for (int off = 16; off; off >>= 1) acc += __shfl_down_sync(0xffffffffu, acc, off);
    if (lane == 0) {
        float p = 1.f / (1.f + expf(-(acc + b_act[0])));
        g_probs[m] = p;
        out_probs[m] = p;
    }
}

// ============ Kernel 4: ACT halting scan (probs staged in smem)
__global__ void k_halt() {
    extern __shared__ float ps[];   // [Bn][Tn+1]
    int tid = threadIdx.x;
    for (int i = tid; i < Bn * Tn; i += 384) {
        int b = i / Tn, t = i - b * Tn;
        ps[b * (Tn + 1) + t] = g_probs[i];
    }
    __syncthreads();
    if (tid < Bn) {
        int b = tid;
        const float* pb = ps + b * (Tn + 1);
        float acc = 0.f;
        int ns = 0;
        for (int t = 0; t < Tn; t++) {
            float p = pb[t];
            float a = acc + p;
            if (a > THRESH) {
                g_weights[b * Tn + t] = p - (a - 1.f);
                g_segend[b * Tn + ns] = t;
                ns++;
                acc = 0.f;
            } else {
                g_weights[b * Tn + t] = p;
                acc = a;
            }
        }
        g_nsegs[b] = ns;
    }
}

// ============ Kernel 5: segment sums -> output embs (zero-padded)
__global__ __launch_bounds__(128) void k_out(float* __restrict__ out) {
    int bs = blockIdx.x;
    int b = bs / Tn, s = bs - b * Tn;
    float* o = out + (size_t)bs * Dn;
    int tid = threadIdx.x;
    if (s >= g_nsegs[b]) {
        for (int d = tid; d < Dn; d += 128) o[d] = 0.f;
        return;
    }
    int t1 = g_segend[b * Tn + s];
    int t0 = (s == 0) ? 0 : g_segend[b * Tn + s - 1] + 1;
    for (int d = tid; d < Dn; d += 128) {
        float sum = 0.f;
        for (int t = t0; t <= t1; t++)
            sum += g_states[(size_t)(b * Tn + t) * Dn + d] * g_weights[b * Tn + t];
        o[d] = sum;
    }
}

extern "C" void kernel_launch(void* const* d_in, const int* in_sizes, int n_in,
                              void* d_out, int out_size) {
    const int* sent    = (const int*)d_in[0];
    const float* emb   = (const float*)d_in[1];
    const float* w_ih  = (const float*)d_in[2];
    const float* w_hh  = (const float*)d_in[3];
    const float* b_ih  = (const float*)d_in[4];
    const float* b_hh  = (const float*)d_in[5];
    const float* w_act = (const float*)d_in[6];
    const float* b_act = (const float*)d_in[7];
    float* out = (float*)d_out;

    cudaFuncSetAttribute(k_gru, cudaFuncAttributeMaxDynamicSharedMemorySize, SMEM_GRU);
    cudaFuncSetAttribute(k_halt, cudaFuncAttributeMaxDynamicSharedMemorySize,
                         Bn * (Tn + 1) * 4);

    k_xp<<<dim3(D3 / BN, (Bn * Tn) / BM), 256>>>(sent, emb, w_ih, b_ih);
    k_gru<<<NB, 256, SMEM_GRU>>>(w_hh, b_hh);
    k_probs<<<(Bn * Tn) / 8, 256>>>(w_act, b_act, out + (size_t)Bn * Tn * Dn);
    k_halt<<<1, 384, Bn * (Tn + 1) * 4>>>();
    k_out<<<Bn * Tn, 128>>>(out);
}